// round 8
// baseline (speedup 1.0000x reference)
#include <cuda_runtime.h>

#define B_   8
#define C_   64
#define NPTS 2048
#define MFRQ 4032
#define F1   2048
#define KC   8

// -------- scratch (device globals; no allocation in kernel_launch) ----------
__device__ __align__(16) float2 g_Xft[B_ * C_ * F1];   // forward result {re, im},  [b][c][f]
__device__ __align__(16) float2 g_xf [B_ * MFRQ * C_]; // Hermitian-expanded {re, -im}, [b][f][c]
__device__ __align__(16) float  g_xT [B_ * NPTS * C_]; // x transposed [b][n][c]
__device__ float2 g_phi[2 * B_ * 1024];                // [mod][b][x(32)][y(32)]

// -------- packed f32x2 helpers ----------------------------------------------
__device__ __forceinline__ unsigned long long pack2(float lo, float hi) {
    unsigned long long r;
    asm("mov.b64 %0, {%1, %2};" : "=l"(r) : "f"(lo), "f"(hi));
    return r;
}
__device__ __forceinline__ float2 unpack2(unsigned long long v) {
    float2 r;
    asm("mov.b64 {%0, %1}, %2;" : "=f"(r.x), "=f"(r.y) : "l"(v));
    return r;
}
__device__ __forceinline__ void fma2(unsigned long long &d,
                                     unsigned long long a,
                                     unsigned long long b) {
    asm("fma.rn.f32x2 %0, %1, %2, %0;" : "+l"(d) : "l"(a), "l"(b));
}
__device__ __forceinline__ void add2(unsigned long long &d, unsigned long long a) {
    asm("add.rn.f32x2 %0, %0, %1;" : "+l"(d) : "l"(a));
}
#define WG_BAR(id) asm volatile("bar.sync %0, 128;" :: "r"(id) : "memory")

// ============================================================================
// Kernel 0: transpose x[b][c][n] -> g_xT[b][n][c]
// ============================================================================
__global__ __launch_bounds__(256) void k_transpose(const float* __restrict__ x)
{
    __shared__ float t[64][65];
    const int b   = blockIdx.y;
    const int n0  = blockIdx.x * 64;
    const int tid = threadIdx.x;

    {
        const int c  = tid >> 2;
        const int nq = (tid & 3) * 16;
        const float4* src = reinterpret_cast<const float4*>(
            x + ((size_t)(b * C_ + c)) * NPTS + n0 + nq);
#pragma unroll
        for (int j = 0; j < 4; j++) {
            float4 v = src[j];
            t[c][nq + 4 * j + 0] = v.x;
            t[c][nq + 4 * j + 1] = v.y;
            t[c][nq + 4 * j + 2] = v.z;
            t[c][nq + 4 * j + 3] = v.w;
        }
    }
    __syncthreads();
    {
        const int n  = tid >> 2;
        const int cq = (tid & 3) * 16;
        float4* dst = reinterpret_cast<float4*>(
            g_xT + ((size_t)(b * NPTS + n0 + n)) * C_ + cq);
#pragma unroll
        for (int j = 0; j < 4; j++) {
            float4 v;
            v.x = t[cq + 4 * j + 0][n];
            v.y = t[cq + 4 * j + 1][n];
            v.z = t[cq + 4 * j + 2][n];
            v.w = t[cq + 4 * j + 3][n];
            dst[j] = v;
        }
    }
}

// ============================================================================
// Kernel 1: phi[b,x,y] = sum_e mod[x,y,e] * emb[b,e]
// ============================================================================
__global__ __launch_bounds__(256) void k_phi(
    const float* __restrict__ emb,
    const float* __restrict__ m1re, const float* __restrict__ m1im,
    const float* __restrict__ m2re, const float* __restrict__ m2im)
{
    __shared__ float s_re[256];
    __shared__ float s_im[256];
    const int bid = blockIdx.x;
    const int mod = bid >> 10;
    const int xy  = bid & 1023;
    const int tid = threadIdx.x;

    const float* mre = (mod ? m2re : m1re) + (size_t)xy * 256;
    const float* mim = (mod ? m2im : m1im) + (size_t)xy * 256;
    s_re[tid] = mre[tid];
    s_im[tid] = mim[tid];
    __syncthreads();

    const int w = tid >> 5;
    const int l = tid & 31;
    float pr = 0.f, pi = 0.f;
#pragma unroll
    for (int j = 0; j < 8; j++) {
        int e = l + j * 32;
        float ee = emb[w * 256 + e];
        pr += s_re[e] * ee;
        pi += s_im[e] * ee;
    }
#pragma unroll
    for (int off = 16; off > 0; off >>= 1) {
        pr += __shfl_down_sync(0xffffffffu, pr, off);
        pi += __shfl_down_sync(0xffffffffu, pi, off);
    }
    if (l == 0) g_phi[mod * (B_ * 1024) + w * 1024 + xy] = make_float2(pr, pi);
}

// ============================================================================
// Kernel 2: forward NUFT. Tile 64f x 64c, 2 blocks/SM, split-K (2 wg),
// 2-stage pipeline, swizzled smem.
// A chunk(ty,i,k): f-pair f0=ty*8+2i at k*512 + i*128 + ((ty+k)&7)*16.
// X chunk(tx,k):  float4 c=tx*4.. at k*256 + ((tx+k)&15)*16.
// Per-thread: 8f x 4c packed accs. grid (32 ftiles, 8 b).
// ============================================================================
__global__ __launch_bounds__(256, 2) void k_forward(
    const float* __restrict__ vfre,
    const float* __restrict__ vfim)
{
    __shared__ __align__(16) char sA[2][2][KC * 512];  // [wg][stage] 16 KB
    __shared__ __align__(16) char sX[2][2][KC * 256];  // [wg][stage]  8 KB

    const int b     = blockIdx.y;
    const int ftile = blockIdx.x;       // 0..31
    const int tid   = threadIdx.x;
    const int wg    = tid >> 7;
    const int wtid  = tid & 127;
    const int tx    = wtid & 15;        // c-group (4 c)
    const int ty    = wtid >> 4;        // f-group (8 f)

    unsigned long long acc[8][4];
#pragma unroll
    for (int i = 0; i < 8; i++)
#pragma unroll
        for (int j = 0; j < 4; j++) acc[i][j] = 0ull;

    const int KHALF = NPTS / 2;         // 1024
    const int kbase = wg * KHALF;

    // A fill role: f-pair fp (0..31), k-pair kq in {0,2,4,6}
    const int fp  = wtid >> 2;
    const int kq  = (wtid & 3) * 2;
    const int fg0 = ftile * 64 + 2 * fp;
    const int fg1 = fg0 + 1;
    const int row0 = (fg0 >> 5) * 63 + (fg0 & 31);
    const int row1 = (fg1 >> 5) * 63 + (fg1 & 31);
    const float* pr0 = vfre + (size_t)row0 * NPTS + kbase + kq;
    const float* pi0 = vfim + (size_t)row0 * NPTS + kbase + kq;
    const float* pr1 = vfre + (size_t)row1 * NPTS + kbase + kq;
    const float* pi1 = vfim + (size_t)row1 * NPTS + kbase + kq;
    const int aoff = (fp & 3) * 128;
    const int ftyp = fp >> 2;           // 0..7

    // X fill role: k-row kx (0..7), c-quad qx (0..15)
    const int kx = wtid >> 4;
    const int qx = wtid & 15;
    const float* xsrc = g_xT + ((size_t)(b * NPTS) + kbase + kx) * C_ + qx * 4;
    const int xoff = kx * 256 + ((qx + kx) & 15) * 16;

    const int bar_id = wg + 1;

    // prefetch kb = 0
    float2 pa = *reinterpret_cast<const float2*>(pr0);
    float2 pb = *reinterpret_cast<const float2*>(pi0);
    float2 pc = *reinterpret_cast<const float2*>(pr1);
    float2 pd = *reinterpret_cast<const float2*>(pi1);
    float4 pxv = *reinterpret_cast<const float4*>(xsrc);

    int stage = 0;
    for (int kb = 0; kb < KHALF; kb += KC) {
        // ---- store prefetched regs into smem[stage] ----
        {
            char* Abase = sA[wg][stage] + aoff;
            float r[2] = {pa.x, pa.y};
            float q[2] = {pb.x, pb.y};
            float s[2] = {pc.x, pc.y};
            float u[2] = {pd.x, pd.y};
#pragma unroll
            for (int j = 0; j < 2; j++) {
                int kk = kq + j;
                *reinterpret_cast<float4*>(Abase + kk * 512 + ((ftyp + kk) & 7) * 16)
                    = make_float4(r[j], q[j], s[j], u[j]);
            }
            *reinterpret_cast<float4*>(sX[wg][stage] + xoff) = pxv;
        }
        // ---- prefetch next block ----
        if (kb + KC < KHALF) {
            pa = *reinterpret_cast<const float2*>(pr0 + kb + KC);
            pb = *reinterpret_cast<const float2*>(pi0 + kb + KC);
            pc = *reinterpret_cast<const float2*>(pr1 + kb + KC);
            pd = *reinterpret_cast<const float2*>(pi1 + kb + KC);
            pxv = *reinterpret_cast<const float4*>(xsrc + (size_t)(kb + KC) * C_);
        }
        WG_BAR(bar_id);

        const char* Aw = sA[wg][stage];
        const char* Xw = sX[wg][stage];
#pragma unroll
        for (int kk = 0; kk < KC; kk++) {
            const char* Ab = Aw + kk * 512;
            const int asw = ((ty + kk) & 7) * 16;
            unsigned long long a[8];
#pragma unroll
            for (int i = 0; i < 4; i++) {
                ulonglong2 t = *reinterpret_cast<const ulonglong2*>(Ab + i * 128 + asw);
                a[2 * i] = t.x; a[2 * i + 1] = t.y;
            }
            float4 x0 = *reinterpret_cast<const float4*>(
                Xw + kk * 256 + ((tx + kk) & 15) * 16);
            unsigned long long xv[4];
            xv[0] = pack2(x0.x, x0.x); xv[1] = pack2(x0.y, x0.y);
            xv[2] = pack2(x0.z, x0.z); xv[3] = pack2(x0.w, x0.w);
#pragma unroll
            for (int fi = 0; fi < 8; fi++)
#pragma unroll
                for (int ci = 0; ci < 4; ci++)
                    fma2(acc[fi][ci], a[fi], xv[ci]);
        }
        stage ^= 1;
    }

    // merge wg1 -> wg0 through smem (reuse sA: 16 KB = 16*128*8)
    unsigned long long* scr = reinterpret_cast<unsigned long long*>(&sA[0][0][0]);
#pragma unroll
    for (int ch = 0; ch < 2; ch++) {
        __syncthreads();
        if (wg == 1) {
#pragma unroll
            for (int j = 0; j < 16; j++) {
                int m = ch * 16 + j;
                scr[j * 128 + wtid] = acc[m >> 2][m & 3];
            }
        }
        __syncthreads();
        if (wg == 0) {
#pragma unroll
            for (int j = 0; j < 16; j++) {
                int m = ch * 16 + j;
                add2(acc[m >> 2][m & 3], scr[j * 128 + wtid]);
            }
        }
    }

    if (wg == 0) {
        const int f0 = ftile * 64 + ty * 8;
#pragma unroll
        for (int ci = 0; ci < 4; ci++) {
            int c = tx * 4 + ci;
            ulonglong2* dst = reinterpret_cast<ulonglong2*>(&g_Xft[((size_t)(b * C_ + c)) * F1 + f0]);
#pragma unroll
            for (int i = 0; i < 4; i++) {
                ulonglong2 t;
                t.x = acc[2 * i][ci];
                t.y = acc[2 * i + 1][ci];
                dst[i] = t;
            }
        }
    }
}

// ============================================================================
// Kernel 3: channel mixing + phi modulation + Hermitian expansion.
// g_xf stored [b][f][c].
// ============================================================================
__global__ __launch_bounds__(512) void k_mix(
    const float* __restrict__ w1re, const float* __restrict__ w1im,
    const float* __restrict__ w2re, const float* __restrict__ w2im)
{
    __shared__ float2 Xs[4][64][16];

    const int bid = blockIdx.x;
    const int xm  = bid >> 2;
    const int yh  = (bid >> 1) & 1;
    const int bh  = bid & 1;
    const int tid = threadIdx.x;

    {
        int row  = tid >> 1;
        int half = tid & 1;
        int br = row >> 6, ii = row & 63;
        const float2* src = g_Xft + ((size_t)((bh * 4 + br) * C_ + ii)) * F1
                            + xm * 32 + yh * 16 + half * 8;
#pragma unroll
        for (int j = 0; j < 4; j++) {
            float4 v = reinterpret_cast<const float4*>(src)[j];
            Xs[br][ii][half * 8 + j * 2]     = make_float2(v.x, v.y);
            Xs[br][ii][half * 8 + j * 2 + 1] = make_float2(v.z, v.w);
        }
    }
    __syncthreads();

    const int o   = tid >> 3;
    const int yq  = tid & 7;
    const int y   = yh * 16 + yq * 2;
    const int x32 = xm & 31;
    const float* wre = (xm < 32) ? w1re : w2re;
    const float* wim = (xm < 32) ? w1im : w2im;

    unsigned long long acc0[4] = {0ull, 0ull, 0ull, 0ull};
    unsigned long long acc1[4] = {0ull, 0ull, 0ull, 0ull};

#pragma unroll 4
    for (int ii = 0; ii < 64; ii++) {
        size_t wrow = (size_t)(ii * 64 + o) * 1024 + x32 * 32 + y;
        float2 wr = *reinterpret_cast<const float2*>(wre + wrow);
        float2 wi = *reinterpret_cast<const float2*>(wim + wrow);
        unsigned long long w0a = pack2(wr.x, wi.x);
        unsigned long long w0b = pack2(-wi.x, wr.x);
        unsigned long long w1a = pack2(wr.y, wi.y);
        unsigned long long w1b = pack2(-wi.y, wr.y);
#pragma unroll
        for (int br = 0; br < 4; br++) {
            float2 xv0 = Xs[br][ii][yq * 2];
            float2 xv1 = Xs[br][ii][yq * 2 + 1];
            fma2(acc0[br], pack2(xv0.x, xv0.x), w0a);
            fma2(acc0[br], pack2(xv0.y, xv0.y), w0b);
            fma2(acc1[br], pack2(xv1.x, xv1.x), w1a);
            fma2(acc1[br], pack2(xv1.y, xv1.y), w1b);
        }
    }

    const int sel = (xm < 32) ? 0 : 1;
#pragma unroll
    for (int br = 0; br < 4; br++) {
        int bb = bh * 4 + br;
#pragma unroll
        for (int pp = 0; pp < 2; pp++) {
            int yy = y + pp;
            float2 s = unpack2(pp ? acc1[br] : acc0[br]);
            float2 p = g_phi[sel * (B_ * 1024) + bb * 1024 + x32 * 32 + yy];
            float vr = p.x * s.x - p.y * s.y;
            float vi = p.x * s.y + p.y * s.x;
            int fm = xm * 32 + yy;
            g_xf[((size_t)bb * MFRQ + fm) * C_ + o] = make_float2(vr, -vi);
            if (fm >= 64)
                g_xf[((size_t)bb * MFRQ + (4095 - fm)) * C_ + (63 - o)] = make_float2(vr, vi);
        }
    }
}

// ============================================================================
// Kernel 4: inverse NUFT (real part), K=4032. Tile 64n x 64c, 2 blocks/SM,
// split-K (2 x 2016), 2-stage pipeline.
// A chunk(ty,i,k): n-pair at k*512 + i*128 + ((ty+k)&7)*16.
// X chunk(tx,i,k): float2 pair c=tx*4+2i at k*512 + i*256 + ((tx+k)&15)*16.
// ============================================================================
__global__ __launch_bounds__(256, 2) void k_inverse(
    const float* __restrict__ vire,
    const float* __restrict__ viim,
    float* __restrict__ out)
{
    __shared__ __align__(16) char sA[2][2][KC * 512];  // 16 KB
    __shared__ __align__(16) char sX[2][2][KC * 512];  // 16 KB

    const int b     = blockIdx.y;
    const int ntile = blockIdx.x;       // 0..31
    const int tid   = threadIdx.x;
    const int wg    = tid >> 7;
    const int wtid  = tid & 127;
    const int tx    = wtid & 15;
    const int ty    = wtid >> 4;

    unsigned long long acc[8][4];
#pragma unroll
    for (int i = 0; i < 8; i++)
#pragma unroll
        for (int j = 0; j < 4; j++) acc[i][j] = 0ull;

    const int KHALF = MFRQ / 2;         // 2016
    const int kbase = wg * KHALF;

    // A fill role
    const int fp = wtid >> 2;
    const int kq = (wtid & 3) * 2;
    const int row0 = ntile * 64 + 2 * fp;
    const float* pr0 = vire + (size_t)row0 * MFRQ + kbase + kq;
    const float* pi0 = viim + (size_t)row0 * MFRQ + kbase + kq;
    const float* pr1 = pr0 + MFRQ;
    const float* pi1 = pi0 + MFRQ;
    const int aoff = (fp & 3) * 128;
    const int ftyp = fp >> 2;

    // X fill role: k-row kx (0..7), c-quad qx (0..15); fills i=0,1 chunks
    const int kx = wtid >> 4;
    const int qx = wtid & 15;
    const float2* xsrc = g_xf + ((size_t)(b * MFRQ) + kbase + kx) * C_ + qx * 4;
    const int xrot = kx * 512 + ((qx + kx) & 15) * 16;

    const int bar_id = wg + 1;

    // prefetch kb = 0
    float2 pa = *reinterpret_cast<const float2*>(pr0);
    float2 pb = *reinterpret_cast<const float2*>(pi0);
    float2 pc = *reinterpret_cast<const float2*>(pr1);
    float2 pd = *reinterpret_cast<const float2*>(pi1);
    float4 px0 = *reinterpret_cast<const float4*>(xsrc);
    float4 px1 = *reinterpret_cast<const float4*>(xsrc + 2);

    int stage = 0;
    for (int kb = 0; kb < KHALF; kb += KC) {
        // ---- store prefetched regs into smem[stage] ----
        {
            char* Abase = sA[wg][stage] + aoff;
            float r[2] = {pa.x, pa.y};
            float q[2] = {pb.x, pb.y};
            float s[2] = {pc.x, pc.y};
            float u[2] = {pd.x, pd.y};
#pragma unroll
            for (int j = 0; j < 2; j++) {
                int kk = kq + j;
                *reinterpret_cast<float4*>(Abase + kk * 512 + ((ftyp + kk) & 7) * 16)
                    = make_float4(r[j], q[j], s[j], u[j]);
            }
            char* Xb = sX[wg][stage] + xrot;
            *reinterpret_cast<float4*>(Xb)       = px0;
            *reinterpret_cast<float4*>(Xb + 256) = px1;
        }
        // ---- prefetch next block ----
        if (kb + KC < KHALF) {
            pa = *reinterpret_cast<const float2*>(pr0 + kb + KC);
            pb = *reinterpret_cast<const float2*>(pi0 + kb + KC);
            pc = *reinterpret_cast<const float2*>(pr1 + kb + KC);
            pd = *reinterpret_cast<const float2*>(pi1 + kb + KC);
            px0 = *reinterpret_cast<const float4*>(xsrc + (size_t)(kb + KC) * C_);
            px1 = *reinterpret_cast<const float4*>(xsrc + (size_t)(kb + KC) * C_ + 2);
        }
        WG_BAR(bar_id);

        const char* Aw = sA[wg][stage];
        const char* Xw = sX[wg][stage];
#pragma unroll
        for (int kk = 0; kk < KC; kk++) {
            const char* Ab = Aw + kk * 512;
            const int asw = ((ty + kk) & 7) * 16;
            unsigned long long a[8];
#pragma unroll
            for (int i = 0; i < 4; i++) {
                ulonglong2 t = *reinterpret_cast<const ulonglong2*>(Ab + i * 128 + asw);
                a[2 * i] = t.x; a[2 * i + 1] = t.y;
            }
            const char* Xb = Xw + kk * 512;
            const int xsw = ((tx + kk) & 15) * 16;
            unsigned long long xv[4];
            {
                ulonglong2 t0 = *reinterpret_cast<const ulonglong2*>(Xb + xsw);
                ulonglong2 t1 = *reinterpret_cast<const ulonglong2*>(Xb + 256 + xsw);
                xv[0] = t0.x; xv[1] = t0.y; xv[2] = t1.x; xv[3] = t1.y;
            }
#pragma unroll
            for (int fi = 0; fi < 8; fi++)
#pragma unroll
                for (int ci = 0; ci < 4; ci++)
                    fma2(acc[fi][ci], a[fi], xv[ci]);
        }
        stage ^= 1;
    }

    // merge wg1 -> wg0
    unsigned long long* scr = reinterpret_cast<unsigned long long*>(&sA[0][0][0]);
#pragma unroll
    for (int ch = 0; ch < 2; ch++) {
        __syncthreads();
        if (wg == 1) {
#pragma unroll
            for (int j = 0; j < 16; j++) {
                int m = ch * 16 + j;
                scr[j * 128 + wtid] = acc[m >> 2][m & 3];
            }
        }
        __syncthreads();
        if (wg == 0) {
#pragma unroll
            for (int j = 0; j < 16; j++) {
                int m = ch * 16 + j;
                add2(acc[m >> 2][m & 3], scr[j * 128 + wtid]);
            }
        }
    }

    if (wg == 0) {
        const float sc = 2.0f / (float)NPTS;
        const int n0 = ntile * 64 + ty * 8;
#pragma unroll
        for (int ci = 0; ci < 4; ci++) {
            int c = tx * 4 + ci;
            float r[8];
#pragma unroll
            for (int fi = 0; fi < 8; fi++) {
                float2 s = unpack2(acc[fi][ci]);
                r[fi] = (s.x + s.y) * sc;
            }
            float4* dst = reinterpret_cast<float4*>(out + ((size_t)(b * C_ + c)) * NPTS + n0);
            dst[0] = make_float4(r[0], r[1], r[2], r[3]);
            dst[1] = make_float4(r[4], r[5], r[6], r[7]);
        }
    }
}

// ============================================================================
extern "C" void kernel_launch(void* const* d_in, const int* in_sizes, int n_in,
                              void* d_out, int out_size)
{
    const float* x     = (const float*)d_in[0];
    const float* emb   = (const float*)d_in[1];
    const float* vf_re = (const float*)d_in[2];
    const float* vf_im = (const float*)d_in[3];
    const float* vi_re = (const float*)d_in[4];
    const float* vi_im = (const float*)d_in[5];
    const float* w1_re = (const float*)d_in[6];
    const float* w1_im = (const float*)d_in[7];
    const float* w2_re = (const float*)d_in[8];
    const float* w2_im = (const float*)d_in[9];
    const float* m1_re = (const float*)d_in[10];
    const float* m1_im = (const float*)d_in[11];
    const float* m2_re = (const float*)d_in[12];
    const float* m2_im = (const float*)d_in[13];
    float* out = (float*)d_out;

    k_phi<<<2048, 256>>>(emb, m1_re, m1_im, m2_re, m2_im);
    k_transpose<<<dim3(32, 8), 256>>>(x);
    k_forward<<<dim3(32, 8), 256>>>(vf_re, vf_im);
    k_mix<<<256, 512>>>(w1_re, w1_im, w2_re, w2_im);
    k_inverse<<<dim3(32, 8), 256>>>(vi_re, vi_im, out);
}

// round 10
// speedup vs baseline: 1.4108x; 1.4108x over previous
#include <cuda_runtime.h>
#include <cstdint>

#define B_   8
#define C_   64
#define NPTS 2048
#define MFRQ 4032
#define F1   2048

// -------- scratch (device globals; no allocation in kernel_launch) ----------
__device__ __align__(16) float2 g_Xft[B_ * C_ * F1];   // forward result {re, im},  [b][c][f]
__device__ __align__(16) float2 g_xf [B_ * C_ * MFRQ]; // Hermitian-expanded {re, -im}, [b][c][f]
__device__ float2 g_phi[2 * B_ * 1024];                // [mod][b][x(32)][y(32)]

// -------- packed f32x2 helpers (k_mix) --------------------------------------
__device__ __forceinline__ unsigned long long pack2(float lo, float hi) {
    unsigned long long r;
    asm("mov.b64 %0, {%1, %2};" : "=l"(r) : "f"(lo), "f"(hi));
    return r;
}
__device__ __forceinline__ float2 unpack2(unsigned long long v) {
    float2 r;
    asm("mov.b64 {%0, %1}, %2;" : "=f"(r.x), "=f"(r.y) : "l"(v));
    return r;
}
__device__ __forceinline__ void fma2(unsigned long long &d,
                                     unsigned long long a,
                                     unsigned long long b) {
    asm("fma.rn.f32x2 %0, %1, %2, %0;" : "+l"(d) : "l"(a), "l"(b));
}

// -------- tf32 mma.sync helpers (arch-portable PTX, compute_80+) ------------
#define SWZ(o) ((o) ^ (((o) >> 3) & 0x70))

__device__ __forceinline__ uint32_t f2tf(float f) {
    uint32_t r;
    asm("cvt.rna.tf32.f32 %0, %1;" : "=r"(r) : "f"(f));
    return r;
}
__device__ __forceinline__ uint4 cvt4(float4 v) {
    uint4 r;
    r.x = f2tf(v.x); r.y = f2tf(v.y); r.z = f2tf(v.z); r.w = f2tf(v.w);
    return r;
}
// D(16x8) += A(16x8) * B(8x8);  A row-major frag, B col-major frag, fp32 accum
__device__ __forceinline__ void mma8(float* d, const uint32_t* a,
                                     uint32_t b0, uint32_t b1) {
    asm volatile(
        "mma.sync.aligned.m16n8k8.row.col.f32.tf32.tf32.f32 "
        "{%0,%1,%2,%3}, {%4,%5,%6,%7}, {%8,%9}, {%0,%1,%2,%3};"
        : "+f"(d[0]), "+f"(d[1]), "+f"(d[2]), "+f"(d[3])
        : "r"(a[0]), "r"(a[1]), "r"(a[2]), "r"(a[3]), "r"(b0), "r"(b1));
}

// ============================================================================
// Kernel 1: phi[b,x,y] = sum_e mod[x,y,e] * emb[b,e]
// ============================================================================
__global__ __launch_bounds__(256) void k_phi(
    const float* __restrict__ emb,
    const float* __restrict__ m1re, const float* __restrict__ m1im,
    const float* __restrict__ m2re, const float* __restrict__ m2im)
{
    __shared__ float s_re[256];
    __shared__ float s_im[256];
    const int bid = blockIdx.x;
    const int mod = bid >> 10;
    const int xy  = bid & 1023;
    const int tid = threadIdx.x;

    const float* mre = (mod ? m2re : m1re) + (size_t)xy * 256;
    const float* mim = (mod ? m2im : m1im) + (size_t)xy * 256;
    s_re[tid] = mre[tid];
    s_im[tid] = mim[tid];
    __syncthreads();

    const int w = tid >> 5;
    const int l = tid & 31;
    float pr = 0.f, pi = 0.f;
#pragma unroll
    for (int j = 0; j < 8; j++) {
        int e = l + j * 32;
        float ee = emb[w * 256 + e];
        pr += s_re[e] * ee;
        pi += s_im[e] * ee;
    }
#pragma unroll
    for (int off = 16; off > 0; off >>= 1) {
        pr += __shfl_down_sync(0xffffffffu, pr, off);
        pi += __shfl_down_sync(0xffffffffu, pi, off);
    }
    if (l == 0) g_phi[mod * (B_ * 1024) + w * 1024 + xy] = make_float2(pr, pi);
}

// ============================================================================
// Forward NUFT via mma.sync tf32: D[f:128, c:64] = Vf_{re|im} @ x[b]^T.
// grid (16 ftiles, 2 reim, 8 b), 128 threads (4 warps), warp tile 64x32.
// Smem: A 128 rows x 32 k (128B SW-swizzled rows), B 64 rows x 32 k.
// ============================================================================
__global__ __launch_bounds__(128) void k_forward(
    const float* __restrict__ x,
    const float* __restrict__ vfre,
    const float* __restrict__ vfim)
{
    __shared__ __align__(16) char sA[2][16384];
    __shared__ __align__(16) char sB[2][8192];

    const int tid  = threadIdx.x;
    const int wid  = tid >> 5;
    const int lane = tid & 31;
    const int g    = lane >> 2;
    const int tig  = lane & 3;
    const int mg   = wid >> 1;      // 0..1 : rows 64*mg
    const int ng   = wid & 1;       // 0..1 : cols 32*ng
    const int ftile = blockIdx.x;
    const int reim  = blockIdx.y;
    const int b     = blockIdx.z;
    const float* vf = reim ? vfim : vfre;
    const float* xb = x + (size_t)b * C_ * NPTS;

    // fill roles: A row = tid (128 rows); B row = tid>>1, half = tid&1
    const int fg   = ftile * 128 + tid;
    const int vrow = (fg >> 5) * 63 + (fg & 31);
    const float* asrc = vf + (size_t)vrow * NPTS;
    const int brow  = tid >> 1;
    const int bhalf = tid & 1;
    const float* bsrc = xb + (size_t)brow * NPTS + bhalf * 16;

    float d[4][4][4];
#pragma unroll
    for (int i = 0; i < 4; i++)
#pragma unroll
        for (int j = 0; j < 4; j++)
#pragma unroll
            for (int k = 0; k < 4; k++) d[i][j][k] = 0.f;

    float4 pa[8], pb[4];
#pragma unroll
    for (int j = 0; j < 8; j++) pa[j] = *(const float4*)(asrc + 4 * j);
#pragma unroll
    for (int j = 0; j < 4; j++) pb[j] = *(const float4*)(bsrc + 4 * j);
    {
        char* Ad = sA[0]; char* Bd = sB[0];
#pragma unroll
        for (int j = 0; j < 8; j++)
            *(uint4*)(Ad + SWZ(tid * 128 + j * 16)) = cvt4(pa[j]);
#pragma unroll
        for (int j = 0; j < 4; j++)
            *(uint4*)(Bd + SWZ(brow * 128 + bhalf * 64 + j * 16)) = cvt4(pb[j]);
    }
    __syncthreads();

    const int NCH = NPTS / 32;      // 64
    int cur = 0;
    for (int i = 0; i < NCH; i++) {
        const bool more = (i + 1 < NCH);
        if (more) {
            const int kb = (i + 1) * 32;
#pragma unroll
            for (int j = 0; j < 8; j++) pa[j] = *(const float4*)(asrc + kb + 4 * j);
#pragma unroll
            for (int j = 0; j < 4; j++) pb[j] = *(const float4*)(bsrc + kb + 4 * j);
        }
        const char* Ab = sA[cur];
        const char* Bb = sB[cur];
#pragma unroll
        for (int kk = 0; kk < 32; kk += 8) {
            uint32_t a[4][4];
#pragma unroll
            for (int mb = 0; mb < 4; mb++) {
                int r0 = mg * 64 + mb * 16 + g;
                a[mb][0] = *(const uint32_t*)(Ab + SWZ(r0 * 128 + (kk + tig) * 4));
                a[mb][1] = *(const uint32_t*)(Ab + SWZ((r0 + 8) * 128 + (kk + tig) * 4));
                a[mb][2] = *(const uint32_t*)(Ab + SWZ(r0 * 128 + (kk + tig + 4) * 4));
                a[mb][3] = *(const uint32_t*)(Ab + SWZ((r0 + 8) * 128 + (kk + tig + 4) * 4));
            }
#pragma unroll
            for (int nb = 0; nb < 4; nb++) {
                int n = ng * 32 + nb * 8 + g;
                uint32_t b0 = *(const uint32_t*)(Bb + SWZ(n * 128 + (kk + tig) * 4));
                uint32_t b1 = *(const uint32_t*)(Bb + SWZ(n * 128 + (kk + tig + 4) * 4));
#pragma unroll
                for (int mb = 0; mb < 4; mb++) mma8(d[mb][nb], a[mb], b0, b1);
            }
        }
        if (more) {
            char* Ad = sA[cur ^ 1]; char* Bd = sB[cur ^ 1];
#pragma unroll
            for (int j = 0; j < 8; j++)
                *(uint4*)(Ad + SWZ(tid * 128 + j * 16)) = cvt4(pa[j]);
#pragma unroll
            for (int j = 0; j < 4; j++)
                *(uint4*)(Bd + SWZ(brow * 128 + bhalf * 64 + j * 16)) = cvt4(pb[j]);
        }
        __syncthreads();
        cur ^= 1;
    }

    // epilogue: scatter D into g_Xft interleaved slot `reim`
    float* dst = reinterpret_cast<float*>(g_Xft) + reim;
#pragma unroll
    for (int mb = 0; mb < 4; mb++) {
#pragma unroll
        for (int nb = 0; nb < 4; nb++) {
            int f0 = ftile * 128 + mg * 64 + mb * 16 + g;
            int c0 = ng * 32 + nb * 8 + 2 * tig;
            dst[((size_t)(b * C_ + c0) * F1 + f0) * 2]           = d[mb][nb][0];
            dst[((size_t)(b * C_ + c0 + 1) * F1 + f0) * 2]       = d[mb][nb][1];
            dst[((size_t)(b * C_ + c0) * F1 + f0 + 8) * 2]       = d[mb][nb][2];
            dst[((size_t)(b * C_ + c0 + 1) * F1 + f0 + 8) * 2]   = d[mb][nb][3];
        }
    }
}

// ============================================================================
// Kernel 3: channel mixing + phi modulation + Hermitian expansion.
// g_xf stored [b][c][f] float2 {re, -im}  (= K-interleaved B operand).
// ============================================================================
__global__ __launch_bounds__(512) void k_mix(
    const float* __restrict__ w1re, const float* __restrict__ w1im,
    const float* __restrict__ w2re, const float* __restrict__ w2im)
{
    __shared__ float2 Xs[4][64][16];

    const int bid = blockIdx.x;
    const int xm  = bid >> 2;
    const int yh  = (bid >> 1) & 1;
    const int bh  = bid & 1;
    const int tid = threadIdx.x;

    {
        int row  = tid >> 1;
        int half = tid & 1;
        int br = row >> 6, ii = row & 63;
        const float2* src = g_Xft + ((size_t)((bh * 4 + br) * C_ + ii)) * F1
                            + xm * 32 + yh * 16 + half * 8;
#pragma unroll
        for (int j = 0; j < 4; j++) {
            float4 v = reinterpret_cast<const float4*>(src)[j];
            Xs[br][ii][half * 8 + j * 2]     = make_float2(v.x, v.y);
            Xs[br][ii][half * 8 + j * 2 + 1] = make_float2(v.z, v.w);
        }
    }
    __syncthreads();

    const int o   = tid >> 3;
    const int yq  = tid & 7;
    const int y   = yh * 16 + yq * 2;
    const int x32 = xm & 31;
    const float* wre = (xm < 32) ? w1re : w2re;
    const float* wim = (xm < 32) ? w1im : w2im;

    unsigned long long acc0[4] = {0ull, 0ull, 0ull, 0ull};
    unsigned long long acc1[4] = {0ull, 0ull, 0ull, 0ull};

#pragma unroll 4
    for (int ii = 0; ii < 64; ii++) {
        size_t wrow = (size_t)(ii * 64 + o) * 1024 + x32 * 32 + y;
        float2 wr = *reinterpret_cast<const float2*>(wre + wrow);
        float2 wi = *reinterpret_cast<const float2*>(wim + wrow);
        unsigned long long w0a = pack2(wr.x, wi.x);
        unsigned long long w0b = pack2(-wi.x, wr.x);
        unsigned long long w1a = pack2(wr.y, wi.y);
        unsigned long long w1b = pack2(-wi.y, wr.y);
#pragma unroll
        for (int br = 0; br < 4; br++) {
            float2 xv0 = Xs[br][ii][yq * 2];
            float2 xv1 = Xs[br][ii][yq * 2 + 1];
            fma2(acc0[br], pack2(xv0.x, xv0.x), w0a);
            fma2(acc0[br], pack2(xv0.y, xv0.y), w0b);
            fma2(acc1[br], pack2(xv1.x, xv1.x), w1a);
            fma2(acc1[br], pack2(xv1.y, xv1.y), w1b);
        }
    }

    const int sel = (xm < 32) ? 0 : 1;
#pragma unroll
    for (int br = 0; br < 4; br++) {
        int bb = bh * 4 + br;
#pragma unroll
        for (int pp = 0; pp < 2; pp++) {
            int yy = y + pp;
            float2 s = unpack2(pp ? acc1[br] : acc0[br]);
            float2 p = g_phi[sel * (B_ * 1024) + bb * 1024 + x32 * 32 + yy];
            float vr = p.x * s.x - p.y * s.y;
            float vi = p.x * s.y + p.y * s.x;
            int fm = xm * 32 + yy;
            g_xf[((size_t)(bb * C_ + o)) * MFRQ + fm] = make_float2(vr, -vi);
            if (fm >= 64)
                g_xf[((size_t)(bb * C_ + (63 - o))) * MFRQ + (4095 - fm)] = make_float2(vr, vi);
        }
    }
}

// ============================================================================
// Inverse NUFT via mma.sync tf32, complex folded into real K-interleaved GEMM:
// D[n:128, c:64] = sum_{2*4032} A[n][.] * B[c][.]
//   A[n][2j,2j+1] = {Vi_re[n,j], Vi_im[n,j]};  B[c][2j,2j+1] = {xf_re, -xf_im}.
// grid (16 ntiles, 8 b), 128 threads, warp tile 64x32. 252 chunks of 16 complex.
// ============================================================================
__global__ __launch_bounds__(128) void k_inverse(
    const float* __restrict__ vire,
    const float* __restrict__ viim,
    float* __restrict__ out)
{
    __shared__ __align__(16) char sA[2][16384];
    __shared__ __align__(16) char sB[2][8192];

    const int tid  = threadIdx.x;
    const int wid  = tid >> 5;
    const int lane = tid & 31;
    const int g    = lane >> 2;
    const int tig  = lane & 3;
    const int mg   = wid >> 1;
    const int ng   = wid & 1;
    const int ntile = blockIdx.x;
    const int b     = blockIdx.y;

    // fill roles: A row = tid; B row = tid>>1, half = tid&1 (8 complex each)
    const float* vre = vire + (size_t)(ntile * 128 + tid) * MFRQ;
    const float* vim = viim + (size_t)(ntile * 128 + tid) * MFRQ;
    const int brow  = tid >> 1;
    const int bhalf = tid & 1;
    const float2* bsrc = g_xf + (size_t)(b * C_ + brow) * MFRQ + bhalf * 8;

    float d[4][4][4];
#pragma unroll
    for (int i = 0; i < 4; i++)
#pragma unroll
        for (int j = 0; j < 4; j++)
#pragma unroll
            for (int k = 0; k < 4; k++) d[i][j][k] = 0.f;

    float4 par[4], pai[4], pb[4];
#pragma unroll
    for (int j = 0; j < 4; j++) {
        par[j] = *(const float4*)(vre + 4 * j);
        pai[j] = *(const float4*)(vim + 4 * j);
        pb[j]  = *(const float4*)(bsrc + 2 * j);
    }
    {
        char* Ad = sA[0]; char* Bd = sB[0];
#pragma unroll
        for (int j = 0; j < 4; j++) {
            uint4 lo = make_uint4(f2tf(par[j].x), f2tf(pai[j].x), f2tf(par[j].y), f2tf(pai[j].y));
            uint4 hi = make_uint4(f2tf(par[j].z), f2tf(pai[j].z), f2tf(par[j].w), f2tf(pai[j].w));
            *(uint4*)(Ad + SWZ(tid * 128 + j * 32))      = lo;
            *(uint4*)(Ad + SWZ(tid * 128 + j * 32 + 16)) = hi;
            *(uint4*)(Bd + SWZ(brow * 128 + bhalf * 64 + j * 16)) = cvt4(pb[j]);
        }
    }
    __syncthreads();

    const int NCH = MFRQ / 16;      // 252
    int cur = 0;
    for (int i = 0; i < NCH; i++) {
        const bool more = (i + 1 < NCH);
        if (more) {
            const int kf = (i + 1) * 16;
#pragma unroll
            for (int j = 0; j < 4; j++) {
                par[j] = *(const float4*)(vre + kf + 4 * j);
                pai[j] = *(const float4*)(vim + kf + 4 * j);
                pb[j]  = *(const float4*)(bsrc + kf + 2 * j);
            }
        }
        const char* Ab = sA[cur];
        const char* Bb = sB[cur];
#pragma unroll
        for (int kk = 0; kk < 32; kk += 8) {
            uint32_t a[4][4];
#pragma unroll
            for (int mb = 0; mb < 4; mb++) {
                int r0 = mg * 64 + mb * 16 + g;
                a[mb][0] = *(const uint32_t*)(Ab + SWZ(r0 * 128 + (kk + tig) * 4));
                a[mb][1] = *(const uint32_t*)(Ab + SWZ((r0 + 8) * 128 + (kk + tig) * 4));
                a[mb][2] = *(const uint32_t*)(Ab + SWZ(r0 * 128 + (kk + tig + 4) * 4));
                a[mb][3] = *(const uint32_t*)(Ab + SWZ((r0 + 8) * 128 + (kk + tig + 4) * 4));
            }
#pragma unroll
            for (int nb = 0; nb < 4; nb++) {
                int n = ng * 32 + nb * 8 + g;
                uint32_t b0 = *(const uint32_t*)(Bb + SWZ(n * 128 + (kk + tig) * 4));
                uint32_t b1 = *(const uint32_t*)(Bb + SWZ(n * 128 + (kk + tig + 4) * 4));
#pragma unroll
                for (int mb = 0; mb < 4; mb++) mma8(d[mb][nb], a[mb], b0, b1);
            }
        }
        if (more) {
            char* Ad = sA[cur ^ 1]; char* Bd = sB[cur ^ 1];
#pragma unroll
            for (int j = 0; j < 4; j++) {
                uint4 lo = make_uint4(f2tf(par[j].x), f2tf(pai[j].x), f2tf(par[j].y), f2tf(pai[j].y));
                uint4 hi = make_uint4(f2tf(par[j].z), f2tf(pai[j].z), f2tf(par[j].w), f2tf(pai[j].w));
                *(uint4*)(Ad + SWZ(tid * 128 + j * 32))      = lo;
                *(uint4*)(Ad + SWZ(tid * 128 + j * 32 + 16)) = hi;
                *(uint4*)(Bd + SWZ(brow * 128 + bhalf * 64 + j * 16)) = cvt4(pb[j]);
            }
        }
        __syncthreads();
        cur ^= 1;
    }

    // epilogue: out[b][c][n] = d * 2/N
    const float sc = 2.0f / (float)NPTS;
#pragma unroll
    for (int mb = 0; mb < 4; mb++) {
#pragma unroll
        for (int nb = 0; nb < 4; nb++) {
            int n0 = ntile * 128 + mg * 64 + mb * 16 + g;
            int c0 = ng * 32 + nb * 8 + 2 * tig;
            out[(size_t)(b * C_ + c0) * NPTS + n0]           = d[mb][nb][0] * sc;
            out[(size_t)(b * C_ + c0 + 1) * NPTS + n0]       = d[mb][nb][1] * sc;
            out[(size_t)(b * C_ + c0) * NPTS + n0 + 8]       = d[mb][nb][2] * sc;
            out[(size_t)(b * C_ + c0 + 1) * NPTS + n0 + 8]   = d[mb][nb][3] * sc;
        }
    }
}

// ============================================================================
extern "C" void kernel_launch(void* const* d_in, const int* in_sizes, int n_in,
                              void* d_out, int out_size)
{
    const float* x     = (const float*)d_in[0];
    const float* emb   = (const float*)d_in[1];
    const float* vf_re = (const float*)d_in[2];
    const float* vf_im = (const float*)d_in[3];
    const float* vi_re = (const float*)d_in[4];
    const float* vi_im = (const float*)d_in[5];
    const float* w1_re = (const float*)d_in[6];
    const float* w1_im = (const float*)d_in[7];
    const float* w2_re = (const float*)d_in[8];
    const float* w2_im = (const float*)d_in[9];
    const float* m1_re = (const float*)d_in[10];
    const float* m1_im = (const float*)d_in[11];
    const float* m2_re = (const float*)d_in[12];
    const float* m2_im = (const float*)d_in[13];
    float* out = (float*)d_out;

    k_phi<<<2048, 256>>>(emb, m1_re, m1_im, m2_re, m2_im);
    k_forward<<<dim3(16, 2, 8), 128>>>(x, vf_re, vf_im);
    k_mix<<<256, 512>>>(w1_re, w1_im, w2_re, w2_im);
    k_inverse<<<dim3(16, 8), 128>>>(vi_re, vi_im, out);
}

// round 11
// speedup vs baseline: 1.7771x; 1.2596x over previous
#include <cuda_runtime.h>
#include <cstdint>

#define B_   8
#define C_   64
#define NPTS 2048
#define MFRQ 4032
#define F1   2048

// -------- scratch (device globals; no allocation in kernel_launch) ----------
__device__ __align__(16) float2 g_Xft[B_ * C_ * F1];   // forward result {re, im},  [b][c][f]
__device__ __align__(16) float2 g_xf [B_ * C_ * MFRQ]; // Hermitian-expanded {re, -im}, [b][c][f]
__device__ float2 g_phi[2 * B_ * 1024];                // [mod][b][x(32)][y(32)]

// -------- packed f32x2 helpers (k_mix) --------------------------------------
__device__ __forceinline__ unsigned long long pack2(float lo, float hi) {
    unsigned long long r;
    asm("mov.b64 %0, {%1, %2};" : "=l"(r) : "f"(lo), "f"(hi));
    return r;
}
__device__ __forceinline__ float2 unpack2(unsigned long long v) {
    float2 r;
    asm("mov.b64 {%0, %1}, %2;" : "=f"(r.x), "=f"(r.y) : "l"(v));
    return r;
}
__device__ __forceinline__ void fma2(unsigned long long &d,
                                     unsigned long long a,
                                     unsigned long long b) {
    asm("fma.rn.f32x2 %0, %1, %2, %0;" : "+l"(d) : "l"(a), "l"(b));
}

// -------- tf32 mma.sync helpers (arch-portable PTX, compute_80+) ------------
#define SWZ(o) ((o) ^ (((o) >> 3) & 0x70))

__device__ __forceinline__ uint32_t f2tf(float f) {
    uint32_t r;
    asm("cvt.rna.tf32.f32 %0, %1;" : "=r"(r) : "f"(f));
    return r;
}
__device__ __forceinline__ uint4 cvt4(float4 v) {
    uint4 r;
    r.x = f2tf(v.x); r.y = f2tf(v.y); r.z = f2tf(v.z); r.w = f2tf(v.w);
    return r;
}
// D(16x8) += A(16x8) * B(8x8);  A row-major frag, B col-major frag, fp32 accum
__device__ __forceinline__ void mma8(float* d, const uint32_t* a,
                                     uint32_t b0, uint32_t b1) {
    asm volatile(
        "mma.sync.aligned.m16n8k8.row.col.f32.tf32.tf32.f32 "
        "{%0,%1,%2,%3}, {%4,%5,%6,%7}, {%8,%9}, {%0,%1,%2,%3};"
        : "+f"(d[0]), "+f"(d[1]), "+f"(d[2]), "+f"(d[3])
        : "r"(a[0]), "r"(a[1]), "r"(a[2]), "r"(a[3]), "r"(b0), "r"(b1));
}

// ============================================================================
// Kernel 1: phi[b,x,y] = sum_e mod[x,y,e] * emb[b,e]
// ============================================================================
__global__ __launch_bounds__(256) void k_phi(
    const float* __restrict__ emb,
    const float* __restrict__ m1re, const float* __restrict__ m1im,
    const float* __restrict__ m2re, const float* __restrict__ m2im)
{
    __shared__ float s_re[256];
    __shared__ float s_im[256];
    const int bid = blockIdx.x;
    const int mod = bid >> 10;
    const int xy  = bid & 1023;
    const int tid = threadIdx.x;

    const float* mre = (mod ? m2re : m1re) + (size_t)xy * 256;
    const float* mim = (mod ? m2im : m1im) + (size_t)xy * 256;
    s_re[tid] = mre[tid];
    s_im[tid] = mim[tid];
    __syncthreads();

    const int w = tid >> 5;
    const int l = tid & 31;
    float pr = 0.f, pi = 0.f;
#pragma unroll
    for (int j = 0; j < 8; j++) {
        int e = l + j * 32;
        float ee = emb[w * 256 + e];
        pr += s_re[e] * ee;
        pi += s_im[e] * ee;
    }
#pragma unroll
    for (int off = 16; off > 0; off >>= 1) {
        pr += __shfl_down_sync(0xffffffffu, pr, off);
        pi += __shfl_down_sync(0xffffffffu, pi, off);
    }
    if (l == 0) g_phi[mod * (B_ * 1024) + w * 1024 + xy] = make_float2(pr, pi);
}

// ============================================================================
// Forward NUFT via mma.sync tf32: D[f:128, c:64] = Vf_{re|im} @ x[b]^T.
// grid (16 ftiles, 2 reim, 8 b), 256 threads (8 warps), warp tile 32x32.
// Smem: A 128 rows x 32 k (128B SW-swizzled rows), B 64 rows x 32 k.
// ============================================================================
__global__ __launch_bounds__(256) void k_forward(
    const float* __restrict__ x,
    const float* __restrict__ vfre,
    const float* __restrict__ vfim)
{
    __shared__ __align__(16) char sA[2][16384];
    __shared__ __align__(16) char sB[2][8192];

    const int tid  = threadIdx.x;
    const int wid  = tid >> 5;
    const int lane = tid & 31;
    const int g    = lane >> 2;
    const int tig  = lane & 3;
    const int mg   = wid >> 1;      // 0..3 : rows 32*mg
    const int ng   = wid & 1;       // 0..1 : cols 32*ng
    const int ftile = blockIdx.x;
    const int reim  = blockIdx.y;
    const int b     = blockIdx.z;
    const float* vf = reim ? vfim : vfre;
    const float* xb = x + (size_t)b * C_ * NPTS;

    // fill roles: A row = tid>>1, half = tid&1 (16 k);  B row = tid>>2, q = tid&3 (8 k)
    const int arow  = tid >> 1;
    const int ahalf = tid & 1;
    const int fg    = ftile * 128 + arow;
    const int vrow  = (fg >> 5) * 63 + (fg & 31);
    const float* asrc = vf + (size_t)vrow * NPTS + ahalf * 16;
    const int brow = tid >> 2;
    const int bq   = tid & 3;
    const float* bsrc = xb + (size_t)brow * NPTS + bq * 8;

    float d[2][4][4];
#pragma unroll
    for (int i = 0; i < 2; i++)
#pragma unroll
        for (int j = 0; j < 4; j++)
#pragma unroll
            for (int k = 0; k < 4; k++) d[i][j][k] = 0.f;

    float4 pa[4], pb[2];
#pragma unroll
    for (int j = 0; j < 4; j++) pa[j] = *(const float4*)(asrc + 4 * j);
#pragma unroll
    for (int j = 0; j < 2; j++) pb[j] = *(const float4*)(bsrc + 4 * j);
    {
        char* Ad = sA[0]; char* Bd = sB[0];
#pragma unroll
        for (int j = 0; j < 4; j++)
            *(uint4*)(Ad + SWZ(arow * 128 + ahalf * 64 + j * 16)) = cvt4(pa[j]);
#pragma unroll
        for (int j = 0; j < 2; j++)
            *(uint4*)(Bd + SWZ(brow * 128 + bq * 32 + j * 16)) = cvt4(pb[j]);
    }
    __syncthreads();

    const int NCH = NPTS / 32;      // 64
    int cur = 0;
    for (int i = 0; i < NCH; i++) {
        const bool more = (i + 1 < NCH);
        if (more) {
            const int kb = (i + 1) * 32;
#pragma unroll
            for (int j = 0; j < 4; j++) pa[j] = *(const float4*)(asrc + kb + 4 * j);
#pragma unroll
            for (int j = 0; j < 2; j++) pb[j] = *(const float4*)(bsrc + kb + 4 * j);
        }
        const char* Ab = sA[cur];
        const char* Bb = sB[cur];
#pragma unroll
        for (int kk = 0; kk < 32; kk += 8) {
            uint32_t a[2][4];
#pragma unroll
            for (int mb = 0; mb < 2; mb++) {
                int r0 = mg * 32 + mb * 16 + g;
                a[mb][0] = *(const uint32_t*)(Ab + SWZ(r0 * 128 + (kk + tig) * 4));
                a[mb][1] = *(const uint32_t*)(Ab + SWZ((r0 + 8) * 128 + (kk + tig) * 4));
                a[mb][2] = *(const uint32_t*)(Ab + SWZ(r0 * 128 + (kk + tig + 4) * 4));
                a[mb][3] = *(const uint32_t*)(Ab + SWZ((r0 + 8) * 128 + (kk + tig + 4) * 4));
            }
#pragma unroll
            for (int nb = 0; nb < 4; nb++) {
                int n = ng * 32 + nb * 8 + g;
                uint32_t b0 = *(const uint32_t*)(Bb + SWZ(n * 128 + (kk + tig) * 4));
                uint32_t b1 = *(const uint32_t*)(Bb + SWZ(n * 128 + (kk + tig + 4) * 4));
#pragma unroll
                for (int mb = 0; mb < 2; mb++) mma8(d[mb][nb], a[mb], b0, b1);
            }
        }
        if (more) {
            char* Ad = sA[cur ^ 1]; char* Bd = sB[cur ^ 1];
#pragma unroll
            for (int j = 0; j < 4; j++)
                *(uint4*)(Ad + SWZ(arow * 128 + ahalf * 64 + j * 16)) = cvt4(pa[j]);
#pragma unroll
            for (int j = 0; j < 2; j++)
                *(uint4*)(Bd + SWZ(brow * 128 + bq * 32 + j * 16)) = cvt4(pb[j]);
        }
        __syncthreads();
        cur ^= 1;
    }

    // epilogue: scatter D into g_Xft interleaved slot `reim`
    float* dst = reinterpret_cast<float*>(g_Xft) + reim;
#pragma unroll
    for (int mb = 0; mb < 2; mb++) {
#pragma unroll
        for (int nb = 0; nb < 4; nb++) {
            int f0 = ftile * 128 + mg * 32 + mb * 16 + g;
            int c0 = ng * 32 + nb * 8 + 2 * tig;
            dst[((size_t)(b * C_ + c0) * F1 + f0) * 2]           = d[mb][nb][0];
            dst[((size_t)(b * C_ + c0 + 1) * F1 + f0) * 2]       = d[mb][nb][1];
            dst[((size_t)(b * C_ + c0) * F1 + f0 + 8) * 2]       = d[mb][nb][2];
            dst[((size_t)(b * C_ + c0 + 1) * F1 + f0 + 8) * 2]   = d[mb][nb][3];
        }
    }
}

// ============================================================================
// Kernel 3: channel mixing + phi modulation + Hermitian expansion.
// g_xf stored [b][c][f] float2 {re, -im}  (= K-interleaved B operand).
// ============================================================================
__global__ __launch_bounds__(512) void k_mix(
    const float* __restrict__ w1re, const float* __restrict__ w1im,
    const float* __restrict__ w2re, const float* __restrict__ w2im)
{
    __shared__ float2 Xs[4][64][16];

    const int bid = blockIdx.x;
    const int xm  = bid >> 2;
    const int yh  = (bid >> 1) & 1;
    const int bh  = bid & 1;
    const int tid = threadIdx.x;

    {
        int row  = tid >> 1;
        int half = tid & 1;
        int br = row >> 6, ii = row & 63;
        const float2* src = g_Xft + ((size_t)((bh * 4 + br) * C_ + ii)) * F1
                            + xm * 32 + yh * 16 + half * 8;
#pragma unroll
        for (int j = 0; j < 4; j++) {
            float4 v = reinterpret_cast<const float4*>(src)[j];
            Xs[br][ii][half * 8 + j * 2]     = make_float2(v.x, v.y);
            Xs[br][ii][half * 8 + j * 2 + 1] = make_float2(v.z, v.w);
        }
    }
    __syncthreads();

    const int o   = tid >> 3;
    const int yq  = tid & 7;
    const int y   = yh * 16 + yq * 2;
    const int x32 = xm & 31;
    const float* wre = (xm < 32) ? w1re : w2re;
    const float* wim = (xm < 32) ? w1im : w2im;

    unsigned long long acc0[4] = {0ull, 0ull, 0ull, 0ull};
    unsigned long long acc1[4] = {0ull, 0ull, 0ull, 0ull};

#pragma unroll 4
    for (int ii = 0; ii < 64; ii++) {
        size_t wrow = (size_t)(ii * 64 + o) * 1024 + x32 * 32 + y;
        float2 wr = *reinterpret_cast<const float2*>(wre + wrow);
        float2 wi = *reinterpret_cast<const float2*>(wim + wrow);
        unsigned long long w0a = pack2(wr.x, wi.x);
        unsigned long long w0b = pack2(-wi.x, wr.x);
        unsigned long long w1a = pack2(wr.y, wi.y);
        unsigned long long w1b = pack2(-wi.y, wr.y);
#pragma unroll
        for (int br = 0; br < 4; br++) {
            float2 xv0 = Xs[br][ii][yq * 2];
            float2 xv1 = Xs[br][ii][yq * 2 + 1];
            fma2(acc0[br], pack2(xv0.x, xv0.x), w0a);
            fma2(acc0[br], pack2(xv0.y, xv0.y), w0b);
            fma2(acc1[br], pack2(xv1.x, xv1.x), w1a);
            fma2(acc1[br], pack2(xv1.y, xv1.y), w1b);
        }
    }

    const int sel = (xm < 32) ? 0 : 1;
#pragma unroll
    for (int br = 0; br < 4; br++) {
        int bb = bh * 4 + br;
#pragma unroll
        for (int pp = 0; pp < 2; pp++) {
            int yy = y + pp;
            float2 s = unpack2(pp ? acc1[br] : acc0[br]);
            float2 p = g_phi[sel * (B_ * 1024) + bb * 1024 + x32 * 32 + yy];
            float vr = p.x * s.x - p.y * s.y;
            float vi = p.x * s.y + p.y * s.x;
            int fm = xm * 32 + yy;
            g_xf[((size_t)(bb * C_ + o)) * MFRQ + fm] = make_float2(vr, -vi);
            if (fm >= 64)
                g_xf[((size_t)(bb * C_ + (63 - o))) * MFRQ + (4095 - fm)] = make_float2(vr, vi);
        }
    }
}

// ============================================================================
// Inverse NUFT via mma.sync tf32, complex folded into real K-interleaved GEMM:
// D[n:128, c:64] = sum_{2*4032} A[n][.] * B[c][.]
//   A[n][2j,2j+1] = {Vi_re[n,j], Vi_im[n,j]};  B[c][2j,2j+1] = {xf_re, -xf_im}.
// grid (16 ntiles, 8 b), 256 threads (8 warps), warp tile 32x32.
// 252 chunks of 16 complex (= 32 real k).
// ============================================================================
__global__ __launch_bounds__(256) void k_inverse(
    const float* __restrict__ vire,
    const float* __restrict__ viim,
    float* __restrict__ out)
{
    __shared__ __align__(16) char sA[2][16384];
    __shared__ __align__(16) char sB[2][8192];

    const int tid  = threadIdx.x;
    const int wid  = tid >> 5;
    const int lane = tid & 31;
    const int g    = lane >> 2;
    const int tig  = lane & 3;
    const int mg   = wid >> 1;      // 0..3
    const int ng   = wid & 1;       // 0..1
    const int ntile = blockIdx.x;
    const int b     = blockIdx.y;

    // fill roles: A row = tid>>1, half = tid&1 (8 complex = 16 real k);
    //             B row = tid>>2, q = tid&3 (4 complex = 8 real k)
    const int arow  = tid >> 1;
    const int ahalf = tid & 1;
    const float* vre = vire + (size_t)(ntile * 128 + arow) * MFRQ + ahalf * 8;
    const float* vim = viim + (size_t)(ntile * 128 + arow) * MFRQ + ahalf * 8;
    const int brow = tid >> 2;
    const int bq   = tid & 3;
    const float2* bsrc = g_xf + (size_t)(b * C_ + brow) * MFRQ + bq * 4;

    float d[2][4][4];
#pragma unroll
    for (int i = 0; i < 2; i++)
#pragma unroll
        for (int j = 0; j < 4; j++)
#pragma unroll
            for (int k = 0; k < 4; k++) d[i][j][k] = 0.f;

    float4 par[2], pai[2], pb[2];
#pragma unroll
    for (int j = 0; j < 2; j++) {
        par[j] = *(const float4*)(vre + 4 * j);
        pai[j] = *(const float4*)(vim + 4 * j);
        pb[j]  = *(const float4*)(bsrc + 2 * j);
    }
    {
        char* Ad = sA[0]; char* Bd = sB[0];
        const int db = arow * 128 + ahalf * 64;
#pragma unroll
        for (int j = 0; j < 2; j++) {
            uint4 lo = make_uint4(f2tf(par[j].x), f2tf(pai[j].x), f2tf(par[j].y), f2tf(pai[j].y));
            uint4 hi = make_uint4(f2tf(par[j].z), f2tf(pai[j].z), f2tf(par[j].w), f2tf(pai[j].w));
            *(uint4*)(Ad + SWZ(db + j * 32))      = lo;
            *(uint4*)(Ad + SWZ(db + j * 32 + 16)) = hi;
            *(uint4*)(Bd + SWZ(brow * 128 + bq * 32 + j * 16)) = cvt4(pb[j]);
        }
    }
    __syncthreads();

    const int NCH = MFRQ / 16;      // 252
    int cur = 0;
    for (int i = 0; i < NCH; i++) {
        const bool more = (i + 1 < NCH);
        if (more) {
            const int kf = (i + 1) * 16;
#pragma unroll
            for (int j = 0; j < 2; j++) {
                par[j] = *(const float4*)(vre + kf + 4 * j);
                pai[j] = *(const float4*)(vim + kf + 4 * j);
                pb[j]  = *(const float4*)(bsrc + kf + 2 * j);
            }
        }
        const char* Ab = sA[cur];
        const char* Bb = sB[cur];
#pragma unroll
        for (int kk = 0; kk < 32; kk += 8) {
            uint32_t a[2][4];
#pragma unroll
            for (int mb = 0; mb < 2; mb++) {
                int r0 = mg * 32 + mb * 16 + g;
                a[mb][0] = *(const uint32_t*)(Ab + SWZ(r0 * 128 + (kk + tig) * 4));
                a[mb][1] = *(const uint32_t*)(Ab + SWZ((r0 + 8) * 128 + (kk + tig) * 4));
                a[mb][2] = *(const uint32_t*)(Ab + SWZ(r0 * 128 + (kk + tig + 4) * 4));
                a[mb][3] = *(const uint32_t*)(Ab + SWZ((r0 + 8) * 128 + (kk + tig + 4) * 4));
            }
#pragma unroll
            for (int nb = 0; nb < 4; nb++) {
                int n = ng * 32 + nb * 8 + g;
                uint32_t b0 = *(const uint32_t*)(Bb + SWZ(n * 128 + (kk + tig) * 4));
                uint32_t b1 = *(const uint32_t*)(Bb + SWZ(n * 128 + (kk + tig + 4) * 4));
#pragma unroll
                for (int mb = 0; mb < 2; mb++) mma8(d[mb][nb], a[mb], b0, b1);
            }
        }
        if (more) {
            char* Ad = sA[cur ^ 1]; char* Bd = sB[cur ^ 1];
            const int db = arow * 128 + ahalf * 64;
#pragma unroll
            for (int j = 0; j < 2; j++) {
                uint4 lo = make_uint4(f2tf(par[j].x), f2tf(pai[j].x), f2tf(par[j].y), f2tf(pai[j].y));
                uint4 hi = make_uint4(f2tf(par[j].z), f2tf(pai[j].z), f2tf(par[j].w), f2tf(pai[j].w));
                *(uint4*)(Ad + SWZ(db + j * 32))      = lo;
                *(uint4*)(Ad + SWZ(db + j * 32 + 16)) = hi;
                *(uint4*)(Bd + SWZ(brow * 128 + bq * 32 + j * 16)) = cvt4(pb[j]);
            }
        }
        __syncthreads();
        cur ^= 1;
    }

    // epilogue: out[b][c][n] = d * 2/N
    const float sc = 2.0f / (float)NPTS;
#pragma unroll
    for (int mb = 0; mb < 2; mb++) {
#pragma unroll
        for (int nb = 0; nb < 4; nb++) {
            int n0 = ntile * 128 + mg * 32 + mb * 16 + g;
            int c0 = ng * 32 + nb * 8 + 2 * tig;
            out[(size_t)(b * C_ + c0) * NPTS + n0]           = d[mb][nb][0] * sc;
            out[(size_t)(b * C_ + c0 + 1) * NPTS + n0]       = d[mb][nb][1] * sc;
            out[(size_t)(b * C_ + c0) * NPTS + n0 + 8]       = d[mb][nb][2] * sc;
            out[(size_t)(b * C_ + c0 + 1) * NPTS + n0 + 8]   = d[mb][nb][3] * sc;
        }
    }
}

// ============================================================================
extern "C" void kernel_launch(void* const* d_in, const int* in_sizes, int n_in,
                              void* d_out, int out_size)
{
    const float* x     = (const float*)d_in[0];
    const float* emb   = (const float*)d_in[1];
    const float* vf_re = (const float*)d_in[2];
    const float* vf_im = (const float*)d_in[3];
    const float* vi_re = (const float*)d_in[4];
    const float* vi_im = (const float*)d_in[5];
    const float* w1_re = (const float*)d_in[6];
    const float* w1_im = (const float*)d_in[7];
    const float* w2_re = (const float*)d_in[8];
    const float* w2_im = (const float*)d_in[9];
    const float* m1_re = (const float*)d_in[10];
    const float* m1_im = (const float*)d_in[11];
    const float* m2_re = (const float*)d_in[12];
    const float* m2_im = (const float*)d_in[13];
    float* out = (float*)d_out;

    k_phi<<<2048, 256>>>(emb, m1_re, m1_im, m2_re, m2_im);
    k_forward<<<dim3(16, 2, 8), 256>>>(x, vf_re, vf_im);
    k_mix<<<256, 512>>>(w1_re, w1_im, w2_re, w2_im);
    k_inverse<<<dim3(16, 8), 256>>>(vi_re, vi_im, out);
}